// round 6
// baseline (speedup 1.0000x reference)
#include <cuda_runtime.h>

// Problem constants
#define BB   1024
#define TT   512
#define II   100
#define IIP  104    // padded input row stride (floats; pad cols never read)
#define HH   150
#define HP   160    // padded hidden (mult of 32)
#define OO   3
#define WP   161    // weight smem pitch (conflict-free transpose fill)
#define XT   32     // xw rows per tile

// rnn kernel geometry
#define K4   152    // padded K (4 chunks of 38)
#define KC   38     // k-chunk per quarter
#define HROW 12     // hs row stride (16B-aligned; rows 7..11 pad)
#define RB   7      // batch rows per rnn CTA (147 CTAs)

// Output tuple layout: out, hidden, logits
#define HID_OFF  ((size_t)BB * TT * OO)
#define LOG_OFF  (HID_OFF + (size_t)BB * TT * HH)

// Scratch: input projection xw[bt][HP] (~335 MB)
__device__ float g_xw[(size_t)BB * TT * HP];

__device__ __forceinline__ unsigned smem_u32(const void* p) {
    return (unsigned)__cvta_generic_to_shared(p);
}

// ---------------------------------------------------------------------------
// Kernel 1: xw[bt][j] = sum_i x[bt][i] * W_ih[j][i].
// R5 compute structure (2 j's x 8 rows per thread) + cp.async double-buffered
// x staging: one barrier per tile, gmem latency fully overlapped, no extra
// register pressure.
// ---------------------------------------------------------------------------
__global__ void __launch_bounds__(320, 2) xw_kernel(const float* __restrict__ x,
                                                    const float* __restrict__ W_ih) {
    extern __shared__ float sm[];
    float* WihT = sm;                 // [II][WP]  (64400 B, 16B-aligned end)
    float* xs0  = sm + II * WP;       // [XT][IIP]
    float* xs1  = xs0 + XT * IIP;     // [XT][IIP]
    const int tid = threadIdx.x;

    for (int i = tid; i < II * WP; i += 320) WihT[i] = 0.f;
    __syncthreads();
    for (int idx = tid; idx < HH * II; idx += 320) {
        const int h = idx / II, i = idx - h * II;
        WihT[i * WP + h] = W_ih[idx];
    }

    const int jp   = tid % 80;        // j pair: {jp, jp+80}
    const int half = tid / 80;        // rows half*8 .. half*8+7
    const int nTiles = (BB * TT) / XT;

    // async-stage helper: 32 rows x 25 16B-chunks (exactly 100 floats/row)
    auto stage = [&](float* dst, int tile) {
        const int bt0 = tile * XT;
#pragma unroll
        for (int s = 0; s < 3; s++) {
            const int c = tid + s * 320;
            if (c < XT * 25) {
                const int r = c / 25, k = c - r * 25;
                const float* src = x + (size_t)(bt0 + r) * II + k * 4;
                const unsigned d = smem_u32(dst + r * IIP + k * 4);
                asm volatile("cp.async.ca.shared.global [%0], [%1], 16;"
                             :: "r"(d), "l"(src));
            }
        }
    };

    // prologue: stage first tile into xs0
    stage(xs0, blockIdx.x);
    asm volatile("cp.async.commit_group;");
    asm volatile("cp.async.wait_group 0;");
    __syncthreads();

    int buf = 0;
    for (int tile = blockIdx.x; tile < nTiles; tile += gridDim.x) {
        const int next = tile + gridDim.x;
        float* cur = buf ? xs1 : xs0;
        float* oth = buf ? xs0 : xs1;
        if (next < nTiles) stage(oth, next);
        asm volatile("cp.async.commit_group;");

        const int bt0 = tile * XT;
        float acc0[8], acc1[8];
#pragma unroll
        for (int r = 0; r < 8; r++) { acc0[r] = 0.f; acc1[r] = 0.f; }

        const float* xrow = cur + half * 8 * IIP;
#pragma unroll
        for (int kq = 0; kq < II / 4; kq++) {
            const float wa0 = WihT[(4 * kq + 0) * WP + jp];
            const float wa1 = WihT[(4 * kq + 1) * WP + jp];
            const float wa2 = WihT[(4 * kq + 2) * WP + jp];
            const float wa3 = WihT[(4 * kq + 3) * WP + jp];
            const float wb0 = WihT[(4 * kq + 0) * WP + jp + 80];
            const float wb1 = WihT[(4 * kq + 1) * WP + jp + 80];
            const float wb2 = WihT[(4 * kq + 2) * WP + jp + 80];
            const float wb3 = WihT[(4 * kq + 3) * WP + jp + 80];
#pragma unroll
            for (int r = 0; r < 8; r++) {
                const float4 xv = *(const float4*)&xrow[r * IIP + 4 * kq];  // broadcast
                acc0[r] = fmaf(xv.x, wa0, acc0[r]);
                acc0[r] = fmaf(xv.y, wa1, acc0[r]);
                acc0[r] = fmaf(xv.z, wa2, acc0[r]);
                acc0[r] = fmaf(xv.w, wa3, acc0[r]);
                acc1[r] = fmaf(xv.x, wb0, acc1[r]);
                acc1[r] = fmaf(xv.y, wb1, acc1[r]);
                acc1[r] = fmaf(xv.z, wb2, acc1[r]);
                acc1[r] = fmaf(xv.w, wb3, acc1[r]);
            }
        }
#pragma unroll
        for (int r = 0; r < 8; r++) {
            const size_t row = (size_t)(bt0 + half * 8 + r);
            g_xw[row * HP + jp]      = acc0[r];
            g_xw[row * HP + jp + 80] = acc1[r];
        }

        asm volatile("cp.async.wait_group 0;");
        __syncthreads();   // one barrier per tile
        buf ^= 1;
    }
}

// ---------------------------------------------------------------------------
// Kernel 2: sequential RNN. 147 CTAs x 7 rows, 640 threads (20 warps,
// 5/5/5/5 SMSP balance). Thread = (j = tid>>2, kc = tid&3): the 4 kc
// partials for a j sit in adjacent lanes -> cross-kc reduction via 2
// shfl_xor butterflies, NO psum smem, ONE barrier per step.
// W_hh[j][38kc..+37] in registers; h transposed hs[k][row], broadcast LDS.
// ---------------------------------------------------------------------------
__global__ void __launch_bounds__(640, 1) rnn_kernel(const float* __restrict__ h0,
                                                     const float* __restrict__ W_hh,
                                                     float* __restrict__ out) {
    __shared__ __align__(16) float hs[2][K4 * HROW];   // [buf][k][row]

    const int tid = threadIdx.x;
    const int j   = tid >> 2;     // [0,160)
    const int kc  = tid & 3;      // k-chunk quarter (adjacent lanes)
    const int b0  = blockIdx.x * RB;
    const int nrows = (BB - b0 < RB) ? (BB - b0) : RB;

    // --- one-time: weights into registers ---
    float w[KC];
#pragma unroll
    for (int i = 0; i < KC; i++) {
        const int k = KC * kc + i;
        w[i] = (j < HH && k < HH) ? W_hh[j * HH + k] : 0.f;
    }

    // --- init hs: zero both buffers, fill valid rows of h0 (transposed) ---
    for (int idx = tid; idx < 2 * K4 * HROW; idx += 640) ((float*)hs)[idx] = 0.f;
    __syncthreads();
    for (int idx = tid; idx < HH * nrows; idx += 640) {
        const int k = idx / nrows, r = idx - k * nrows;
        hs[0][k * HROW + r] = h0[(b0 + r) * HH + k];
    }
    __syncthreads();

    // reduction rows for this thread: r_lo = kc (0..3), r_hi = kc+4 (kc<3)
    const int r_lo = kc;
    const int r_hi = kc + 4;
    const bool v_lo = (r_lo < nrows);
    const bool v_hi = (kc < 3) && (r_hi < nrows);
    const int row_lo = v_lo ? r_lo : 0;   // clamp for safe addressing
    const int row_hi = v_hi ? r_hi : 0;
    const float* px0 = g_xw + ((size_t)(b0 + row_lo) * TT) * HP + j;
    const float* px1 = g_xw + ((size_t)(b0 + row_hi) * TT) * HP + j;
    float xw0 = px0[0];
    float xw1 = px1[0];

    float* hid_out = out + HID_OFF;
    int cur = 0;

    for (int t = 0; t < TT; t++) {
        // prefetch next step's xw (latency hidden by FMA loop)
        float nx0 = 0.f, nx1 = 0.f;
        if (t + 1 < TT) { nx0 = px0[HP]; nx1 = px1[HP]; }

        // --- main FMA loop: 7 rows x 38 k, weights in regs, h broadcast ---
        const float* hc = &hs[cur][(KC * kc) * HROW];
        float a0 = 0.f, a1 = 0.f, a2 = 0.f, a3 = 0.f;
        float a4 = 0.f, a5 = 0.f, a6 = 0.f;
#pragma unroll
        for (int i = 0; i < KC; i++) {
            const float4 va = *(const float4*)(hc + i * HROW);
            const float4 vb = *(const float4*)(hc + i * HROW + 4);
            a0 = fmaf(w[i], va.x, a0);
            a1 = fmaf(w[i], va.y, a1);
            a2 = fmaf(w[i], va.z, a2);
            a3 = fmaf(w[i], va.w, a3);
            a4 = fmaf(w[i], vb.x, a4);
            a5 = fmaf(w[i], vb.y, a5);
            a6 = fmaf(w[i], vb.z, a6);
        }

        // --- butterfly reduce across kc (adjacent 4 lanes) ---
        a0 += __shfl_xor_sync(0xffffffffu, a0, 1);
        a0 += __shfl_xor_sync(0xffffffffu, a0, 2);
        a1 += __shfl_xor_sync(0xffffffffu, a1, 1);
        a1 += __shfl_xor_sync(0xffffffffu, a1, 2);
        a2 += __shfl_xor_sync(0xffffffffu, a2, 1);
        a2 += __shfl_xor_sync(0xffffffffu, a2, 2);
        a3 += __shfl_xor_sync(0xffffffffu, a3, 1);
        a3 += __shfl_xor_sync(0xffffffffu, a3, 2);
        a4 += __shfl_xor_sync(0xffffffffu, a4, 1);
        a4 += __shfl_xor_sync(0xffffffffu, a4, 2);
        a5 += __shfl_xor_sync(0xffffffffu, a5, 1);
        a5 += __shfl_xor_sync(0xffffffffu, a5, 2);
        a6 += __shfl_xor_sync(0xffffffffu, a6, 1);
        a6 += __shfl_xor_sync(0xffffffffu, a6, 2);

        // this thread finalizes rows r_lo (and r_hi if kc<3)
        float s0 = (kc == 0) ? a0 : (kc == 1) ? a1 : (kc == 2) ? a2 : a3;
        s0 = fmaxf(s0 + xw0, 0.f);
        float s1 = (kc == 0) ? a4 : (kc == 1) ? a5 : a6;
        s1 = fmaxf(s1 + xw1, 0.f);

        // --- write next h state (transposed) + hidden output ---
        float* hn = hs[cur ^ 1];
        if (j < HH) {
            hn[j * HROW + r_lo] = s0;
            if (v_lo) hid_out[((size_t)(b0 + r_lo) * TT + t) * HH + j] = s0;
            if (kc < 3) {
                hn[j * HROW + r_hi] = s1;
                if (v_hi) hid_out[((size_t)(b0 + r_hi) * TT + t) * HH + j] = s1;
            }
        }

        xw0 = nx0; xw1 = nx1;
        px0 += HP; px1 += HP;
        __syncthreads();   // single barrier per step
        cur ^= 1;
    }
}

// ---------------------------------------------------------------------------
// Kernel 3: logits = hidden @ W_fc^T; out = one_hot(argmax(logits+g)).
// ---------------------------------------------------------------------------
__global__ void __launch_bounds__(256) post_kernel(const float* __restrict__ g,
                                                   const float* __restrict__ W_fc,
                                                   float* __restrict__ out) {
    __shared__ float wfc[OO * HP];
    const int tid = threadIdx.x;
    for (int i = tid; i < OO * HP; i += 256) {
        const int o = i / HP, k = i - o * HP;
        wfc[i] = (k < HH) ? W_fc[o * HH + k] : 0.f;
    }
    __syncthreads();

    const int warp = tid >> 5, lane = tid & 31;
    const size_t bt = (size_t)blockIdx.x * 8 + warp;
    const float* hid = out + HID_OFF + bt * HH;

    float hv[5];
#pragma unroll
    for (int m = 0; m < 5; m++) {
        const int k = lane + 32 * m;
        hv[m] = (k < HH) ? hid[k] : 0.f;
    }
    float p[OO];
#pragma unroll
    for (int o = 0; o < OO; o++) {
        float s = 0.f;
#pragma unroll
        for (int m = 0; m < 5; m++)
            s = fmaf(hv[m], wfc[o * HP + lane + 32 * m], s);
#pragma unroll
        for (int off = 16; off > 0; off >>= 1)
            s += __shfl_xor_sync(0xffffffffu, s, off);
        p[o] = s;
    }
    if (lane == 0) {
        const float z0 = p[0] + g[bt * OO + 0];
        const float z1 = p[1] + g[bt * OO + 1];
        const float z2 = p[2] + g[bt * OO + 2];
        int idx = 0; float best = z0;
        if (z1 > best) { best = z1; idx = 1; }
        if (z2 > best) { best = z2; idx = 2; }
        float* op = out + bt * OO;
        op[0] = (idx == 0) ? 1.f : 0.f;
        op[1] = (idx == 1) ? 1.f : 0.f;
        op[2] = (idx == 2) ? 1.f : 0.f;
        float* lp = out + LOG_OFF + bt * OO;
        lp[0] = p[0]; lp[1] = p[1]; lp[2] = p[2];
    }
}

// ---------------------------------------------------------------------------
extern "C" void kernel_launch(void* const* d_in, const int* in_sizes, int n_in,
                              void* d_out, int out_size) {
    const float* x    = (const float*)d_in[0];
    const float* h0   = (const float*)d_in[1];
    const float* g    = (const float*)d_in[2];
    const float* W_ih = (const float*)d_in[3];
    const float* W_hh = (const float*)d_in[4];
    const float* W_fc = (const float*)d_in[5];
    float* out = (float*)d_out;

    const int xw_smem = (II * WP + 2 * XT * IIP) * (int)sizeof(float);   // ~91 KB
    cudaFuncSetAttribute(xw_kernel, cudaFuncAttributeMaxDynamicSharedMemorySize, xw_smem);

    xw_kernel<<<2048, 320, xw_smem>>>(x, W_ih);
    rnn_kernel<<<(BB + RB - 1) / RB, 640>>>(h0, W_hh, out);   // 147 CTAs
    post_kernel<<<(BB * TT) / 8, 256>>>(g, W_fc, out);
}

// round 7
// speedup vs baseline: 1.5296x; 1.5296x over previous
#include <cuda_runtime.h>

// Problem constants
#define BB   1024
#define TT   512
#define II   100
#define IIP  104    // padded input row stride (floats)
#define HH   150
#define HP   160    // padded hidden (mult of 32)
#define OO   3
#define WP   161    // weight smem pitch (conflict-free transpose fill)
#define XT   32     // xw rows per tile

// rnn kernel geometry
#define K4   152    // padded K (4 chunks of 38)
#define KC   38     // k-chunk per quarter
#define HROW 12     // hs row stride (16B-aligned; rows 7..11 pad)
#define RB   7      // batch rows per rnn CTA (147 CTAs)

// Output tuple layout: out, hidden, logits
#define HID_OFF  ((size_t)BB * TT * OO)
#define LOG_OFF  (HID_OFF + (size_t)BB * TT * HH)

// Scratch: input projection xw[bt][HP] (~335 MB)
__device__ float g_xw[(size_t)BB * TT * HP];

__device__ __forceinline__ unsigned smem_u32(const void* p) {
    return (unsigned)__cvta_generic_to_shared(p);
}

// ---------------------------------------------------------------------------
// Kernel 1: xw[bt][j] = sum_i x[bt][i] * W_ih[j][i].
// 2 j's x 8 rows per thread; cp.async double-buffered x staging (measured
// 493us in R6 — keep).
// ---------------------------------------------------------------------------
__global__ void __launch_bounds__(320, 2) xw_kernel(const float* __restrict__ x,
                                                    const float* __restrict__ W_ih) {
    extern __shared__ float sm[];
    float* WihT = sm;                 // [II][WP]
    float* xs0  = sm + II * WP;       // [XT][IIP]
    float* xs1  = xs0 + XT * IIP;     // [XT][IIP]
    const int tid = threadIdx.x;

    for (int i = tid; i < II * WP; i += 320) WihT[i] = 0.f;
    __syncthreads();
    for (int idx = tid; idx < HH * II; idx += 320) {
        const int h = idx / II, i = idx - h * II;
        WihT[i * WP + h] = W_ih[idx];
    }

    const int jp   = tid % 80;        // j pair: {jp, jp+80}
    const int half = tid / 80;        // rows half*8 .. half*8+7
    const int nTiles = (BB * TT) / XT;

    auto stage = [&](float* dst, int tile) {
        const int bt0 = tile * XT;
#pragma unroll
        for (int s = 0; s < 3; s++) {
            const int c = tid + s * 320;
            if (c < XT * 25) {
                const int r = c / 25, k = c - r * 25;
                const float* src = x + (size_t)(bt0 + r) * II + k * 4;
                const unsigned d = smem_u32(dst + r * IIP + k * 4);
                asm volatile("cp.async.ca.shared.global [%0], [%1], 16;"
                             :: "r"(d), "l"(src));
            }
        }
    };

    stage(xs0, blockIdx.x);
    asm volatile("cp.async.commit_group;");
    asm volatile("cp.async.wait_group 0;");
    __syncthreads();

    int buf = 0;
    for (int tile = blockIdx.x; tile < nTiles; tile += gridDim.x) {
        const int next = tile + gridDim.x;
        float* cur = buf ? xs1 : xs0;
        float* oth = buf ? xs0 : xs1;
        if (next < nTiles) stage(oth, next);
        asm volatile("cp.async.commit_group;");

        const int bt0 = tile * XT;
        float acc0[8], acc1[8];
#pragma unroll
        for (int r = 0; r < 8; r++) { acc0[r] = 0.f; acc1[r] = 0.f; }

        const float* xrow = cur + half * 8 * IIP;
#pragma unroll
        for (int kq = 0; kq < II / 4; kq++) {
            const float wa0 = WihT[(4 * kq + 0) * WP + jp];
            const float wa1 = WihT[(4 * kq + 1) * WP + jp];
            const float wa2 = WihT[(4 * kq + 2) * WP + jp];
            const float wa3 = WihT[(4 * kq + 3) * WP + jp];
            const float wb0 = WihT[(4 * kq + 0) * WP + jp + 80];
            const float wb1 = WihT[(4 * kq + 1) * WP + jp + 80];
            const float wb2 = WihT[(4 * kq + 2) * WP + jp + 80];
            const float wb3 = WihT[(4 * kq + 3) * WP + jp + 80];
#pragma unroll
            for (int r = 0; r < 8; r++) {
                const float4 xv = *(const float4*)&xrow[r * IIP + 4 * kq];  // broadcast
                acc0[r] = fmaf(xv.x, wa0, acc0[r]);
                acc0[r] = fmaf(xv.y, wa1, acc0[r]);
                acc0[r] = fmaf(xv.z, wa2, acc0[r]);
                acc0[r] = fmaf(xv.w, wa3, acc0[r]);
                acc1[r] = fmaf(xv.x, wb0, acc1[r]);
                acc1[r] = fmaf(xv.y, wb1, acc1[r]);
                acc1[r] = fmaf(xv.z, wb2, acc1[r]);
                acc1[r] = fmaf(xv.w, wb3, acc1[r]);
            }
        }
#pragma unroll
        for (int r = 0; r < 8; r++) {
            const size_t row = (size_t)(bt0 + half * 8 + r);
            g_xw[row * HP + jp]      = acc0[r];
            g_xw[row * HP + jp + 80] = acc1[r];
        }

        asm volatile("cp.async.wait_group 0;");
        __syncthreads();
        buf ^= 1;
    }
}

// ---------------------------------------------------------------------------
// Kernel 2: sequential RNN (R5 psum design — measured 1007us; warp-uniform
// broadcast LDS is load-bearing: j = tid%HP keeps all 32 lanes of a warp on
// the SAME smem address in the FMA loop -> 1 wavefront per LDS.128).
// 147 CTAs x 7 rows, 640 threads. Thread=(j,kc) holds W_hh[j][38kc..+37]
// in registers. Cross-kc reduction via smem psum, 2 barriers/step.
// ---------------------------------------------------------------------------
__global__ void __launch_bounds__(640, 1) rnn_kernel(const float* __restrict__ h0,
                                                     const float* __restrict__ W_hh,
                                                     float* __restrict__ out) {
    __shared__ __align__(16) float hs[2][K4 * HROW];   // [buf][k][row]
    __shared__ float psum[4][RB * HP];                  // [kc][r*HP+j]

    const int tid = threadIdx.x;
    const int j   = tid % HP;
    const int kc  = tid / HP;
    const int b0  = blockIdx.x * RB;
    const int nrows = (BB - b0 < RB) ? (BB - b0) : RB;

    float w[KC];
#pragma unroll
    for (int i = 0; i < KC; i++) {
        const int k = KC * kc + i;
        w[i] = (j < HH && k < HH) ? W_hh[j * HH + k] : 0.f;
    }

    for (int idx = tid; idx < 2 * K4 * HROW; idx += 640) ((float*)hs)[idx] = 0.f;
    __syncthreads();
    for (int idx = tid; idx < HH * nrows; idx += 640) {
        const int k = idx / nrows, r = idx - k * nrows;
        hs[0][k * HROW + r] = h0[(b0 + r) * HH + k];
    }
    __syncthreads();

    const int r_lo = kc;
    const int r_hi = kc + 4;
    const bool v_lo = (r_lo < nrows);
    const bool v_hi = (kc < 3) && (r_hi < nrows);
    const int row_lo = v_lo ? r_lo : 0;
    const int row_hi = v_hi ? r_hi : 0;
    const float* px0 = g_xw + ((size_t)(b0 + row_lo) * TT) * HP + j;
    const float* px1 = g_xw + ((size_t)(b0 + row_hi) * TT) * HP + j;
    float xw0 = px0[0];
    float xw1 = px1[0];

    float* hid_out = out + HID_OFF;
    int cur = 0;

    for (int t = 0; t < TT; t++) {
        float nx0 = 0.f, nx1 = 0.f;
        if (t + 1 < TT) { nx0 = px0[HP]; nx1 = px1[HP]; }

        const float* hc = &hs[cur][(KC * kc) * HROW];
        float a0 = 0.f, a1 = 0.f, a2 = 0.f, a3 = 0.f;
        float a4 = 0.f, a5 = 0.f, a6 = 0.f;
#pragma unroll
        for (int i = 0; i < KC; i++) {
            const float4 va = *(const float4*)(hc + i * HROW);   // warp-uniform broadcast
            const float4 vb = *(const float4*)(hc + i * HROW + 4);
            a0 = fmaf(w[i], va.x, a0);
            a1 = fmaf(w[i], va.y, a1);
            a2 = fmaf(w[i], va.z, a2);
            a3 = fmaf(w[i], va.w, a3);
            a4 = fmaf(w[i], vb.x, a4);
            a5 = fmaf(w[i], vb.y, a5);
            a6 = fmaf(w[i], vb.z, a6);
        }

        float* ps = psum[kc] + j;
        ps[0 * HP] = a0; ps[1 * HP] = a1; ps[2 * HP] = a2; ps[3 * HP] = a3;
        ps[4 * HP] = a4; ps[5 * HP] = a5; ps[6 * HP] = a6;
        __syncthreads();

        float s0 = psum[0][r_lo * HP + j] + psum[1][r_lo * HP + j]
                 + psum[2][r_lo * HP + j] + psum[3][r_lo * HP + j] + xw0;
        s0 = fmaxf(s0, 0.f);
        float s1 = 0.f;
        if (kc < 3) {
            s1 = psum[0][r_hi * HP + j] + psum[1][r_hi * HP + j]
               + psum[2][r_hi * HP + j] + psum[3][r_hi * HP + j] + xw1;
            s1 = fmaxf(s1, 0.f);
        }

        float* hn = hs[cur ^ 1];
        if (j < HH) {
            if (v_lo) {
                hn[j * HROW + r_lo] = s0;
                hid_out[((size_t)(b0 + r_lo) * TT + t) * HH + j] = s0;
            }
            if (v_hi) {
                hn[j * HROW + r_hi] = s1;
                hid_out[((size_t)(b0 + r_hi) * TT + t) * HH + j] = s1;
            }
        }

        xw0 = nx0; xw1 = nx1;
        px0 += HP; px1 += HP;
        __syncthreads();
        cur ^= 1;
    }
}

// ---------------------------------------------------------------------------
// Kernel 3: logits = hidden @ W_fc^T; out = one_hot(argmax(logits+g)).
// ---------------------------------------------------------------------------
__global__ void __launch_bounds__(256) post_kernel(const float* __restrict__ g,
                                                   const float* __restrict__ W_fc,
                                                   float* __restrict__ out) {
    __shared__ float wfc[OO * HP];
    const int tid = threadIdx.x;
    for (int i = tid; i < OO * HP; i += 256) {
        const int o = i / HP, k = i - o * HP;
        wfc[i] = (k < HH) ? W_fc[o * HH + k] : 0.f;
    }
    __syncthreads();

    const int warp = tid >> 5, lane = tid & 31;
    const size_t bt = (size_t)blockIdx.x * 8 + warp;
    const float* hid = out + HID_OFF + bt * HH;

    float hv[5];
#pragma unroll
    for (int m = 0; m < 5; m++) {
        const int k = lane + 32 * m;
        hv[m] = (k < HH) ? hid[k] : 0.f;
    }
    float p[OO];
#pragma unroll
    for (int o = 0; o < OO; o++) {
        float s = 0.f;
#pragma unroll
        for (int m = 0; m < 5; m++)
            s = fmaf(hv[m], wfc[o * HP + lane + 32 * m], s);
#pragma unroll
        for (int off = 16; off > 0; off >>= 1)
            s += __shfl_xor_sync(0xffffffffu, s, off);
        p[o] = s;
    }
    if (lane == 0) {
        const float z0 = p[0] + g[bt * OO + 0];
        const float z1 = p[1] + g[bt * OO + 1];
        const float z2 = p[2] + g[bt * OO + 2];
        int idx = 0; float best = z0;
        if (z1 > best) { best = z1; idx = 1; }
        if (z2 > best) { best = z2; idx = 2; }
        float* op = out + bt * OO;
        op[0] = (idx == 0) ? 1.f : 0.f;
        op[1] = (idx == 1) ? 1.f : 0.f;
        op[2] = (idx == 2) ? 1.f : 0.f;
        float* lp = out + LOG_OFF + bt * OO;
        lp[0] = p[0]; lp[1] = p[1]; lp[2] = p[2];
    }
}

// ---------------------------------------------------------------------------
extern "C" void kernel_launch(void* const* d_in, const int* in_sizes, int n_in,
                              void* d_out, int out_size) {
    const float* x    = (const float*)d_in[0];
    const float* h0   = (const float*)d_in[1];
    const float* g    = (const float*)d_in[2];
    const float* W_ih = (const float*)d_in[3];
    const float* W_hh = (const float*)d_in[4];
    const float* W_fc = (const float*)d_in[5];
    float* out = (float*)d_out;

    const int xw_smem = (II * WP + 2 * XT * IIP) * (int)sizeof(float);   // ~91 KB
    cudaFuncSetAttribute(xw_kernel, cudaFuncAttributeMaxDynamicSharedMemorySize, xw_smem);

    xw_kernel<<<2048, 320, xw_smem>>>(x, W_ih);
    rnn_kernel<<<(BB + RB - 1) / RB, 640>>>(h0, W_hh, out);   // 147 CTAs
    post_kernel<<<(BB * TT) / 8, 256>>>(g, W_fc, out);
}